// round 3
// baseline (speedup 1.0000x reference)
#include <cuda_runtime.h>
#include <math.h>

// Problem constants
#define Bsz   4
#define Ssz   4096
#define Esz   1024
#define Hsz   16
#define DHsz  64
#define WSZv  64
#define TOPKv 8
#define NWv   (Ssz / WSZv)          // 64 windows
#define Msz   (Bsz * Ssz)           // 16384 rows for projections

// Scratch (no cudaMalloc allowed): __device__ globals, referenced directly
// by name inside kernels.
__device__ float g_q [Bsz * Hsz * Ssz * DHsz];
__device__ float g_k [Bsz * Hsz * Ssz * DHsz];
__device__ float g_v [Bsz * Hsz * Ssz * DHsz];
__device__ float g_ao[Bsz * Hsz * Ssz * DHsz];
__device__ float g_qn[Bsz * Hsz * DHsz];
__device__ float g_sc[Bsz * Hsz * NWv];
__device__ int   g_sel[Bsz * Hsz * TOPKv];
__device__ float g_lc [Bsz * Hsz * TOPKv];

// ---------------------------------------------------------------------------
// GEMM: C[M,N] = A[M,K] @ W[N,K]^T + bias[N]
// MODE 0/2/3: A plain row-major [M,K]; result stored permuted into the
//             (B,H,S,DH) layout of g_q / g_k / g_v respectively.
// MODE 1:     A gathered from g_ao in (B,H,S,DH) layout; C plain [M,N].
// Block tile 128x128x16, 256 threads, 8x8 register tile per thread.
// ---------------------------------------------------------------------------
#define BM 128
#define BN 128
#define BK 16

template <int MODE>
__global__ __launch_bounds__(256) void gemm_nt_kernel(
    const float* __restrict__ A, const float* __restrict__ W,
    const float* __restrict__ bias, float* __restrict__ C)
{
    const int K = Esz;
    __shared__ __align__(16) float As[BK][BM];
    __shared__ __align__(16) float Ws[BK][BN];

    const int bm  = blockIdx.y * BM;
    const int bn  = blockIdx.x * BN;
    const int tid = threadIdx.x;
    const int tx  = tid & 15;   // n-dim
    const int ty  = tid >> 4;   // m-dim

    float acc[8][8];
#pragma unroll
    for (int i = 0; i < 8; i++)
#pragma unroll
        for (int j = 0; j < 8; j++) acc[i][j] = 0.f;

    for (int k0 = 0; k0 < K; k0 += BK) {
#pragma unroll
        for (int l = 0; l < 2; l++) {
            const int f   = tid + l * 256;       // 0..511 float4 slots
            const int row = f >> 2;              // 0..127
            const int kq  = (f & 3) * 4;         // 0,4,8,12
            const int gk  = k0 + kq;

            float4 av;
            if (MODE != 1) {
                av = *reinterpret_cast<const float4*>(A + (size_t)(bm + row) * K + gk);
            } else {
                // gather from g_ao (B,H,S,DH): m = b*S+s ; col = h*64+d
                const int gm = bm + row;
                const int b  = gm >> 12;                 // /4096
                const int s  = gm & 4095;
                const float* p = g_ao + (((size_t)(b * Hsz + (gk >> 6)) * Ssz + s) << 6) + (gk & 63);
                av = *reinterpret_cast<const float4*>(p);
            }
            As[kq + 0][row] = av.x; As[kq + 1][row] = av.y;
            As[kq + 2][row] = av.z; As[kq + 3][row] = av.w;

            float4 wv = *reinterpret_cast<const float4*>(W + (size_t)(bn + row) * K + gk);
            Ws[kq + 0][row] = wv.x; Ws[kq + 1][row] = wv.y;
            Ws[kq + 2][row] = wv.z; Ws[kq + 3][row] = wv.w;
        }
        __syncthreads();

#pragma unroll
        for (int kk = 0; kk < BK; kk++) {
            float4 a0 = *reinterpret_cast<const float4*>(&As[kk][ty * 8]);
            float4 a1 = *reinterpret_cast<const float4*>(&As[kk][ty * 8 + 4]);
            float4 b0 = *reinterpret_cast<const float4*>(&Ws[kk][tx * 8]);
            float4 b1 = *reinterpret_cast<const float4*>(&Ws[kk][tx * 8 + 4]);
            float af[8] = {a0.x, a0.y, a0.z, a0.w, a1.x, a1.y, a1.z, a1.w};
            float bf[8] = {b0.x, b0.y, b0.z, b0.w, b1.x, b1.y, b1.z, b1.w};
#pragma unroll
            for (int i = 0; i < 8; i++)
#pragma unroll
                for (int j = 0; j < 8; j++) acc[i][j] = fmaf(af[i], bf[j], acc[i][j]);
        }
        __syncthreads();
    }

    // Epilogue
#pragma unroll
    for (int i = 0; i < 8; i++) {
        const int gm = bm + ty * 8 + i;
#pragma unroll
        for (int jq = 0; jq < 2; jq++) {
            const int gn = bn + tx * 8 + jq * 4;
            float4 r;
            r.x = acc[i][jq * 4 + 0] + bias[gn + 0];
            r.y = acc[i][jq * 4 + 1] + bias[gn + 1];
            r.z = acc[i][jq * 4 + 2] + bias[gn + 2];
            r.w = acc[i][jq * 4 + 3] + bias[gn + 3];
            if (MODE == 1) {
                *reinterpret_cast<float4*>(C + (size_t)gm * Esz + gn) = r;
            } else {
                const int b = gm >> 12, s = gm & 4095;
                const int h = gn >> 6,  d = gn & 63;
                const size_t off = (((size_t)(b * Hsz + h) * Ssz + s) << 6) + d;
                float* dst = (MODE == 0) ? g_q : (MODE == 2) ? g_k : g_v;
                *reinterpret_cast<float4*>(dst + off) = r;
            }
        }
    }
}

// ---------------------------------------------------------------------------
// Mean query per (b,h), normalized. grid = B*H, block = 512 (8 s-rows x 64 d)
// ---------------------------------------------------------------------------
__global__ void qmean_kernel()
{
    const int bh  = blockIdx.x;
    const int tid = threadIdx.x;
    const int d   = tid & 63;
    const int r   = tid >> 6;   // 0..7
    const float* base = g_q + ((size_t)bh * Ssz << 6);

    float sum = 0.f;
    for (int s = r; s < Ssz; s += 8) sum += base[(s << 6) + d];

    __shared__ float sm[8][64];
    sm[r][d] = sum;
    __syncthreads();
    if (r == 0) {
        float tot = 0.f;
#pragma unroll
        for (int i = 0; i < 8; i++) tot += sm[i][d];
        sm[0][d] = tot / (float)Ssz;
    }
    __syncthreads();
    __shared__ float nrm;
    if (tid == 0) {
        float ss = 0.f;
#pragma unroll
        for (int i = 0; i < 64; i++) ss += sm[0][i] * sm[0][i];
        nrm = fmaxf(sqrtf(ss), 1e-12f);
    }
    __syncthreads();
    if (r == 0) g_qn[bh * 64 + d] = sm[0][d] / nrm;
}

// ---------------------------------------------------------------------------
// Window scores: score[bh,n] = (1/W) * sum_w (qn . k_w/||k_w||)^2 / max(temp,.01)
// grid = B*H*NW, block = 256
// ---------------------------------------------------------------------------
__global__ void score_kernel(const float* __restrict__ temp)
{
    const int g  = blockIdx.x;
    const int bh = g / NWv;
    const int n  = g % NWv;

    __shared__ __align__(16) float kw[64 * 64];
    __shared__ float qs[64];
    __shared__ float red[64];

    const float* kbase = g_k + ((size_t)bh * Ssz << 6) + (n << 12);
    for (int i = threadIdx.x; i < 64 * 64 / 4; i += 256)
        reinterpret_cast<float4*>(kw)[i] = reinterpret_cast<const float4*>(kbase)[i];
    if (threadIdx.x < 64) qs[threadIdx.x] = g_qn[bh * 64 + threadIdx.x];
    __syncthreads();

    if (threadIdx.x < 64) {
        const int w = threadIdx.x;
        float dot = 0.f, ss = 0.f;
#pragma unroll
        for (int d = 0; d < 64; d++) {
            float kv = kw[w * 64 + d];
            dot = fmaf(qs[d], kv, dot);
            ss  = fmaf(kv, kv, ss);
        }
        float dn = dot / fmaxf(sqrtf(ss), 1e-12f);
        red[w] = dn * dn;
    }
    __syncthreads();
    if (threadIdx.x == 0) {
        float s = 0.f;
#pragma unroll
        for (int i = 0; i < 64; i++) s += red[i];
        s = s / (float)WSZv / fmaxf(temp[0], 0.01f);
        g_sc[g] = s;
    }
}

// ---------------------------------------------------------------------------
// Top-8 of 64 + coarse softmax + log. grid = B*H, 32 threads (thread 0 works)
// ---------------------------------------------------------------------------
__global__ void topk_kernel()
{
    if (threadIdx.x != 0) return;
    const int bh = blockIdx.x;
    float sc[NWv];
    for (int i = 0; i < NWv; i++) sc[i] = g_sc[bh * NWv + i];

    float top[TOPKv]; int idx[TOPKv];
    for (int t = 0; t < TOPKv; t++) {
        float best = -1e30f; int bi = 0;
        for (int i = 0; i < NWv; i++)
            if (sc[i] > best) { best = sc[i]; bi = i; }
        top[t] = best; idx[t] = bi; sc[bi] = -1e30f;
    }
    const float m = top[0];
    float den = 0.f, e[TOPKv];
    for (int t = 0; t < TOPKv; t++) { e[t] = expf(top[t] - m); den += e[t]; }
    for (int t = 0; t < TOPKv; t++) {
        g_sel[bh * TOPKv + t] = idx[t];
        g_lc [bh * TOPKv + t] = logf(e[t] / den + 1e-6f);
    }
}

// ---------------------------------------------------------------------------
// Sparse attention over 8 selected windows (512 keys), online softmax.
// grid = (S/128, B*H), block = 128; one query per thread.
// ---------------------------------------------------------------------------
__global__ __launch_bounds__(128) void attn_kernel()
{
    const int bh  = blockIdx.y;
    const int tid = threadIdx.x;
    const int myq = blockIdx.x * 128 + tid;
    const float SCALE = 0.125f;   // 64^-0.5

    const float* qp = g_q + ((size_t)bh * Ssz << 6) + ((size_t)myq << 6);
    float qv[64];
#pragma unroll
    for (int d = 0; d < 64; d += 4) {
        float4 t = *reinterpret_cast<const float4*>(qp + d);
        qv[d] = t.x; qv[d + 1] = t.y; qv[d + 2] = t.z; qv[d + 3] = t.w;
    }

    float acc[64];
#pragma unroll
    for (int d = 0; d < 64; d++) acc[d] = 0.f;
    float m = -1e30f, l = 0.f;

    __shared__ __align__(16) float ks[64 * 64];
    __shared__ __align__(16) float vs[64 * 64];

    for (int t = 0; t < TOPKv; t++) {
        const int   n   = g_sel[bh * TOPKv + t];
        const float lcv = g_lc [bh * TOPKv + t];
        const float* kb = g_k + ((size_t)bh * Ssz << 6) + ((size_t)n << 12);
        const float* vb = g_v + ((size_t)bh * Ssz << 6) + ((size_t)n << 12);

        __syncthreads();
        for (int i = tid; i < 1024; i += 128) {
            reinterpret_cast<float4*>(ks)[i] = reinterpret_cast<const float4*>(kb)[i];
            reinterpret_cast<float4*>(vs)[i] = reinterpret_cast<const float4*>(vb)[i];
        }
        __syncthreads();

        for (int j = 0; j < 64; j++) {
            float dot = 0.f;
#pragma unroll
            for (int d = 0; d < 64; d += 4) {
                float4 kk = *reinterpret_cast<const float4*>(&ks[j * 64 + d]);
                dot = fmaf(qv[d], kk.x, dot);
                dot = fmaf(qv[d + 1], kk.y, dot);
                dot = fmaf(qv[d + 2], kk.z, dot);
                dot = fmaf(qv[d + 3], kk.w, dot);
            }
            const float logit = fmaf(dot, SCALE, lcv);
            if (logit > m) {
                const float corr = expf(m - logit);
                l *= corr;
#pragma unroll
                for (int d = 0; d < 64; d++) acc[d] *= corr;
                m = logit;
            }
            const float p = expf(logit - m);
            l += p;
#pragma unroll
            for (int d = 0; d < 64; d += 4) {
                float4 vv = *reinterpret_cast<const float4*>(&vs[j * 64 + d]);
                acc[d]     = fmaf(p, vv.x, acc[d]);
                acc[d + 1] = fmaf(p, vv.y, acc[d + 1]);
                acc[d + 2] = fmaf(p, vv.z, acc[d + 2]);
                acc[d + 3] = fmaf(p, vv.w, acc[d + 3]);
            }
        }
    }

    const float inv = 1.f / l;
    float* op = g_ao + ((size_t)bh * Ssz << 6) + ((size_t)myq << 6);
#pragma unroll
    for (int d = 0; d < 64; d += 4) {
        float4 r = make_float4(acc[d] * inv, acc[d + 1] * inv, acc[d + 2] * inv, acc[d + 3] * inv);
        *reinterpret_cast<float4*>(op + d) = r;
    }
}

// ---------------------------------------------------------------------------
extern "C" void kernel_launch(void* const* d_in, const int* in_sizes, int n_in,
                              void* d_out, int out_size)
{
    const float* query = (const float*)d_in[0];
    const float* key   = (const float*)d_in[1];
    const float* value = (const float*)d_in[2];
    const float* Wq    = (const float*)d_in[3];
    const float* bq    = (const float*)d_in[4];
    const float* Wk    = (const float*)d_in[5];
    const float* bk    = (const float*)d_in[6];
    const float* Wv    = (const float*)d_in[7];
    const float* bv    = (const float*)d_in[8];
    const float* Wo    = (const float*)d_in[9];
    const float* bo    = (const float*)d_in[10];
    const float* temp  = (const float*)d_in[11];
    float* out = (float*)d_out;

    dim3 ggrid(Esz / BN, Msz / BM);   // (8, 128)

    gemm_nt_kernel<0><<<ggrid, 256>>>(query, Wq, bq, nullptr);
    gemm_nt_kernel<2><<<ggrid, 256>>>(key,   Wk, bk, nullptr);
    gemm_nt_kernel<3><<<ggrid, 256>>>(value, Wv, bv, nullptr);

    qmean_kernel<<<Bsz * Hsz, 512>>>();
    score_kernel<<<Bsz * Hsz * NWv, 256>>>(temp);
    topk_kernel<<<Bsz * Hsz, 32>>>();

    attn_kernel<<<dim3(Ssz / 128, Bsz * Hsz), 128>>>();

    gemm_nt_kernel<1><<<ggrid, 256>>>(nullptr, Wo, bo, out);
}

// round 9
// speedup vs baseline: 1.6151x; 1.6151x over previous
#include <cuda_runtime.h>
#include <cuda_bf16.h>
#include <math.h>
#include <stdint.h>

// Problem constants
#define Bsz   4
#define Ssz   4096
#define Esz   1024
#define Hsz   16
#define DHsz  64
#define WSZv  64
#define TOPKv 8
#define NWv   (Ssz / WSZv)          // 64 windows
#define Msz   (Bsz * Ssz)           // 16384 rows for projections

// ---------------- scratch (__device__ globals; no cudaMalloc) --------------
__device__ float g_q [Bsz * Hsz * Ssz * DHsz];
__device__ float g_k [Bsz * Hsz * Ssz * DHsz];
__device__ float g_v [Bsz * Hsz * Ssz * DHsz];
__device__ float g_ao[Bsz * Hsz * Ssz * DHsz];
__device__ float g_qn[Bsz * Hsz * DHsz];
__device__ float g_sc[Bsz * Hsz * NWv];
__device__ int   g_sel[Bsz * Hsz * TOPKv];
__device__ float g_lc [Bsz * Hsz * TOPKv];

// bf16 split buffers (reused across the 4 GEMMs, stream-serial)
__device__ __nv_bfloat16 g_ah[Msz * Esz];
__device__ __nv_bfloat16 g_al[Msz * Esz];
__device__ __nv_bfloat16 g_wh[Esz * Esz];
__device__ __nv_bfloat16 g_wl[Esz * Esz];

// ---------------- PTX helpers (baseline sm_100: mma.sync / ldmatrix) -------
__device__ __forceinline__ uint32_t smem_u32(const void* p) {
    uint32_t a;
    asm("{ .reg .u64 t; cvta.to.shared.u64 t, %1; cvt.u32.u64 %0, t; }" : "=r"(a) : "l"(p));
    return a;
}

#define CP_ASYNC16(dst, src) \
    asm volatile("cp.async.cg.shared.global [%0], [%1], 16;\n" :: "r"(dst), "l"(src))
#define CP_COMMIT() asm volatile("cp.async.commit_group;\n" ::: "memory")
#define CP_WAIT(n)  asm volatile("cp.async.wait_group %0;\n" :: "n"(n) : "memory")

#define LDM_X4(r0, r1, r2, r3, a) \
    asm volatile("ldmatrix.sync.aligned.m8n8.x4.shared.b16 {%0,%1,%2,%3}, [%4];" \
        : "=r"(r0), "=r"(r1), "=r"(r2), "=r"(r3) : "r"(a))

// B fragment via plain 32-bit shared loads (no ldmatrix needed):
// lane l needs W[n=l>>2][k=(l&3)*2,+1] -> single aligned 4B word.
#define LDS32(r, a) \
    asm volatile("ld.shared.b32 %0, [%1];" : "=r"(r) : "r"(a))

#define MMA_BF16(d, a0, a1, a2, a3, b0, b1) \
    asm volatile("mma.sync.aligned.m16n8k16.row.col.f32.bf16.bf16.f32 " \
        "{%0,%1,%2,%3}, {%4,%5,%6,%7}, {%8,%9}, {%0,%1,%2,%3};" \
        : "+f"((d)[0]), "+f"((d)[1]), "+f"((d)[2]), "+f"((d)[3]) \
        : "r"(a0), "r"(a1), "r"(a2), "r"(a3), "r"(b0), "r"(b1))

// ---------------------------------------------------------------------------
// bf16 split converters (template-selected destinations)
// ---------------------------------------------------------------------------
__device__ __forceinline__ void split1(float v, unsigned short& h, unsigned short& l)
{
    __nv_bfloat16 hb = __float2bfloat16(v);
    float r = v - __bfloat162float(hb);
    __nv_bfloat16 lb = __float2bfloat16(r);
    h = *reinterpret_cast<unsigned short*>(&hb);
    l = *reinterpret_cast<unsigned short*>(&lb);
}

// DST 0: (g_ah, g_al)   DST 1: (g_wh, g_wl)
template <int DST>
__global__ void split_kernel(const float* __restrict__ src, int n4)
{
    int i = blockIdx.x * blockDim.x + threadIdx.x;
    if (i >= n4) return;
    float4 v = reinterpret_cast<const float4*>(src)[i];
    ushort4 hh, ll;
    split1(v.x, hh.x, ll.x);
    split1(v.y, hh.y, ll.y);
    split1(v.z, hh.z, ll.z);
    split1(v.w, hh.w, ll.w);
    __nv_bfloat16* dh = (DST == 0) ? g_ah : g_wh;
    __nv_bfloat16* dl = (DST == 0) ? g_al : g_wl;
    *reinterpret_cast<ushort4*>(dh + (size_t)i * 4) = hh;
    *reinterpret_cast<ushort4*>(dl + (size_t)i * 4) = ll;
}

// g_ao (B,H,S,DH) -> plain [M=16384, K=1024] (m = b*S+s, col = h*64+d), split
__global__ void split_ao_kernel()
{
    int i = blockIdx.x * blockDim.x + threadIdx.x;   // 0 .. 16384*256-1
    const int m  = i >> 8;
    const int c4 = i & 255;
    const int b = m >> 12, s = m & 4095;
    const int h = c4 >> 4, d = (c4 & 15) * 4;
    const float* p = g_ao + (((size_t)(b * Hsz + h) * Ssz + s) << 6) + d;
    float4 v = *reinterpret_cast<const float4*>(p);
    ushort4 hh, ll;
    split1(v.x, hh.x, ll.x);
    split1(v.y, hh.y, ll.y);
    split1(v.z, hh.z, ll.z);
    split1(v.w, hh.w, ll.w);
    const size_t o = (size_t)m * Esz + c4 * 4;
    *reinterpret_cast<ushort4*>(g_ah + o) = hh;
    *reinterpret_cast<ushort4*>(g_al + o) = ll;
}

// ---------------------------------------------------------------------------
// GEMM via mma.sync bf16x3: C[M,N] = A[M,K] @ W[N,K]^T + bias
// MODE 0/2/3: epilogue stores fp32 permuted into g_q / g_k / g_v.
// MODE 1:     epilogue stores plain row-major [M,1024] into C.
// CTA tile 128x128x16, 256 threads (8 warps, 2Mx4N), warp tile 64x32,
// 2-stage cp.async double buffer, STATIC 48KB shared.
// ---------------------------------------------------------------------------
#define GBM 128
#define GBN 128
#define GKC 16
#define NKB (Esz / GKC)            // 64 k-blocks
#define ROWB   48                  // padded row stride (bytes) for 32B rows
#define T_SZ   (128 * ROWB)        // 6144 B per tensor tile
#define ST_SZ  (4 * T_SZ)          // Ah, Al, Bh, Bl = 24576 B per stage
#define SMEM_GEMM (2 * ST_SZ)      // 49152 B = 48KB (static limit)

template <int MODE>
__global__ __launch_bounds__(256) void gemm_mma_kernel(
    const float* __restrict__ bias, float* __restrict__ C)
{
    __shared__ __align__(16) char smem[SMEM_GEMM];
    const uint32_t sb = smem_u32(smem);
    const int tid  = threadIdx.x;
    const int lane = tid & 31;
    const int wid  = tid >> 5;
    const int wm   = wid & 1;          // 0..1  (M)
    const int wn   = wid >> 1;         // 0..3  (N)
    const int bm   = blockIdx.y * GBM;
    const int bn   = blockIdx.x * GBN;

    const char* gsrc[4] = {
        (const char*)(g_ah + (size_t)bm * Esz),
        (const char*)(g_al + (size_t)bm * Esz),
        (const char*)(g_wh + (size_t)bn * Esz),
        (const char*)(g_wl + (size_t)bn * Esz)
    };

    // 4 tensors x 128 rows x 2 chunks(16B) = 1024 chunks; 4 per thread
    auto load_stage = [&](int kb, int st) {
        const uint32_t stage = sb + st * ST_SZ;
        const size_t kbyte = (size_t)kb * (GKC * 2);   // 32 bytes per k-block
#pragma unroll
        for (int t = 0; t < 4; ++t) {
            const int c      = tid + t * 256;
            const int tensor = c >> 8;
            const int w      = c & 255;
            const int row    = w >> 1;
            const int ch     = w & 1;
            const char* s = gsrc[tensor] + (size_t)row * (Esz * 2) + kbyte + ch * 16;
            const uint32_t d = stage + tensor * T_SZ + row * ROWB + ch * 16;
            CP_ASYNC16(d, s);
        }
        CP_COMMIT();
    };

    float acc[4][4][4];
#pragma unroll
    for (int m = 0; m < 4; m++)
#pragma unroll
        for (int n = 0; n < 4; n++)
#pragma unroll
            for (int e = 0; e < 4; e++) acc[m][n][e] = 0.f;

    // per-lane address components
    const int aRow  = wm * 64 + (lane & 15);       // + m*16 (ldmatrix A)
    const int aColB = (lane >> 4) * 16;            // 0 or 16 within 32B row
    const int bRowL = wn * 32 + (lane >> 2);       // + n*8 (W row = n index)
    const int bColL = (lane & 3) * 4;              // byte offset for k-pair

    load_stage(0, 0);
    load_stage(1, 1);

#pragma unroll 1
    for (int i = 0; i < NKB; ++i) {
        const int st = i & 1;
        if (i == NKB - 1) { CP_WAIT(0); } else { CP_WAIT(1); }
        __syncthreads();

        const uint32_t stage = sb + st * ST_SZ;
        const uint32_t sAh = stage;
        const uint32_t sAl = stage + T_SZ;
        const uint32_t sBh = stage + 2 * T_SZ;
        const uint32_t sBl = stage + 3 * T_SZ;

        uint32_t ah[4][4], al[4][4], bh[4][2], bl[4][2];
#pragma unroll
        for (int m = 0; m < 4; ++m) {
            const uint32_t ra = (uint32_t)(aRow + m * 16) * ROWB + aColB;
            LDM_X4(ah[m][0], ah[m][1], ah[m][2], ah[m][3], sAh + ra);
            LDM_X4(al[m][0], al[m][1], al[m][2], al[m][3], sAl + ra);
        }
#pragma unroll
        for (int n = 0; n < 4; ++n) {
            const uint32_t rb = (uint32_t)(bRowL + n * 8) * ROWB + bColL;
            LDS32(bh[n][0], sBh + rb);        // k0-7 pair
            LDS32(bh[n][1], sBh + rb + 16);   // k8-15 pair
            LDS32(bl[n][0], sBl + rb);
            LDS32(bl[n][1], sBl + rb + 16);
        }
#pragma unroll
        for (int m = 0; m < 4; ++m)
#pragma unroll
            for (int n = 0; n < 4; ++n) {
                MMA_BF16(acc[m][n], ah[m][0], ah[m][1], ah[m][2], ah[m][3],
                         bh[n][0], bh[n][1]);
                MMA_BF16(acc[m][n], ah[m][0], ah[m][1], ah[m][2], ah[m][3],
                         bl[n][0], bl[n][1]);
                MMA_BF16(acc[m][n], al[m][0], al[m][1], al[m][2], al[m][3],
                         bh[n][0], bh[n][1]);
            }

        __syncthreads();
        if (i + 2 < NKB) load_stage(i + 2, st);
    }

    // Epilogue: frag (m,n): lane holds rows l/4 and l/4+8, cols (l%4)*2, +1
#pragma unroll
    for (int m = 0; m < 4; ++m) {
        const int gm0 = bm + wm * 64 + m * 16 + (lane >> 2);
#pragma unroll
        for (int n = 0; n < 4; ++n) {
            const int col = bn + wn * 32 + n * 8 + (lane & 3) * 2;
            const float bx = __ldg(bias + col);
            const float by = __ldg(bias + col + 1);
#pragma unroll
            for (int half = 0; half < 2; ++half) {
                const int gm = gm0 + half * 8;
                float2 r;
                r.x = acc[m][n][half * 2 + 0] + bx;
                r.y = acc[m][n][half * 2 + 1] + by;
                if (MODE == 1) {
                    *reinterpret_cast<float2*>(C + (size_t)gm * Esz + col) = r;
                } else {
                    const int b = gm >> 12, s = gm & 4095;
                    const int h = col >> 6, d = col & 63;
                    float* dst = (MODE == 0) ? g_q : (MODE == 2) ? g_k : g_v;
                    *reinterpret_cast<float2*>(
                        dst + (((size_t)(b * Hsz + h) * Ssz + s) << 6) + d) = r;
                }
            }
        }
    }
}

// ---------------------------------------------------------------------------
// Mean query per (b,h), normalized. grid = B*H, block = 512
// ---------------------------------------------------------------------------
__global__ void qmean_kernel()
{
    const int bh  = blockIdx.x;
    const int tid = threadIdx.x;
    const int d   = tid & 63;
    const int r   = tid >> 6;
    const float* base = g_q + ((size_t)bh * Ssz << 6);

    float sum = 0.f;
    for (int s = r; s < Ssz; s += 8) sum += base[(s << 6) + d];

    __shared__ float sm[8][64];
    sm[r][d] = sum;
    __syncthreads();
    if (r == 0) {
        float tot = 0.f;
#pragma unroll
        for (int i = 0; i < 8; i++) tot += sm[i][d];
        sm[0][d] = tot / (float)Ssz;
    }
    __syncthreads();
    __shared__ float nrm;
    if (tid == 0) {
        float ss = 0.f;
#pragma unroll
        for (int i = 0; i < 64; i++) ss += sm[0][i] * sm[0][i];
        nrm = fmaxf(sqrtf(ss), 1e-12f);
    }
    __syncthreads();
    if (r == 0) g_qn[bh * 64 + d] = sm[0][d] / nrm;
}

// ---------------------------------------------------------------------------
// Window scores
// ---------------------------------------------------------------------------
__global__ void score_kernel(const float* __restrict__ temp)
{
    const int g  = blockIdx.x;
    const int bh = g / NWv;
    const int n  = g % NWv;

    __shared__ __align__(16) float kw[64 * 64];
    __shared__ float qs[64];
    __shared__ float red[64];

    const float* kbase = g_k + ((size_t)bh * Ssz << 6) + (n << 12);
    for (int i = threadIdx.x; i < 64 * 64 / 4; i += 256)
        reinterpret_cast<float4*>(kw)[i] = reinterpret_cast<const float4*>(kbase)[i];
    if (threadIdx.x < 64) qs[threadIdx.x] = g_qn[bh * 64 + threadIdx.x];
    __syncthreads();

    if (threadIdx.x < 64) {
        const int w = threadIdx.x;
        float dot = 0.f, ss = 0.f;
#pragma unroll
        for (int d = 0; d < 64; d++) {
            float kv = kw[w * 64 + d];
            dot = fmaf(qs[d], kv, dot);
            ss  = fmaf(kv, kv, ss);
        }
        float dn = dot / fmaxf(sqrtf(ss), 1e-12f);
        red[w] = dn * dn;
    }
    __syncthreads();
    if (threadIdx.x == 0) {
        float s = 0.f;
#pragma unroll
        for (int i = 0; i < 64; i++) s += red[i];
        s = s / (float)WSZv / fmaxf(temp[0], 0.01f);
        g_sc[g] = s;
    }
}

// ---------------------------------------------------------------------------
// Top-8 of 64 + coarse softmax + log
// ---------------------------------------------------------------------------
__global__ void topk_kernel()
{
    if (threadIdx.x != 0) return;
    const int bh = blockIdx.x;
    float sc[NWv];
    for (int i = 0; i < NWv; i++) sc[i] = g_sc[bh * NWv + i];

    float top[TOPKv]; int idx[TOPKv];
    for (int t = 0; t < TOPKv; t++) {
        float best = -1e30f; int bi = 0;
        for (int i = 0; i < NWv; i++)
            if (sc[i] > best) { best = sc[i]; bi = i; }
        top[t] = best; idx[t] = bi; sc[bi] = -1e30f;
    }
    const float m = top[0];
    float den = 0.f, e[TOPKv];
    for (int t = 0; t < TOPKv; t++) { e[t] = expf(top[t] - m); den += e[t]; }
    for (int t = 0; t < TOPKv; t++) {
        g_sel[bh * TOPKv + t] = idx[t];
        g_lc [bh * TOPKv + t] = logf(e[t] / den + 1e-6f);
    }
}

// ---------------------------------------------------------------------------
// Sparse attention over 8 selected windows (512 keys), online softmax.
// ---------------------------------------------------------------------------
__global__ __launch_bounds__(128) void attn_kernel()
{
    const int bh  = blockIdx.y;
    const int tid = threadIdx.x;
    const int myq = blockIdx.x * 128 + tid;
    const float SCALE = 0.125f;

    const float* qp = g_q + ((size_t)bh * Ssz << 6) + ((size_t)myq << 6);
    float qv[64];
#pragma unroll
    for (int d = 0; d < 64; d += 4) {
        float4 t = *reinterpret_cast<const float4*>(qp + d);
        qv[d] = t.x; qv[d + 1] = t.y; qv[d + 2] = t.z; qv[d + 3] = t.w;
    }

    float acc[64];
#pragma unroll
    for (int d = 0; d < 64; d++) acc[d] = 0.f;
    float m = -1e30f, l = 0.f;

    __shared__ __align__(16) float ks[64 * 64];
    __shared__ __align__(16) float vs[64 * 64];

    for (int t = 0; t < TOPKv; t++) {
        const int   n   = g_sel[bh * TOPKv + t];
        const float lcv = g_lc [bh * TOPKv + t];
        const float* kb = g_k + ((size_t)bh * Ssz << 6) + ((size_t)n << 12);
        const float* vb = g_v + ((size_t)bh * Ssz << 6) + ((size_t)n << 12);

        __syncthreads();
        for (int i = tid; i < 1024; i += 128) {
            reinterpret_cast<float4*>(ks)[i] = reinterpret_cast<const float4*>(kb)[i];
            reinterpret_cast<float4*>(vs)[i] = reinterpret_cast<const float4*>(vb)[i];
        }
        __syncthreads();

        for (int j = 0; j < 64; j++) {
            float dot = 0.f;
#pragma unroll
            for (int d = 0; d < 64; d += 4) {
                float4 kk = *reinterpret_cast<const float4*>(&ks[j * 64 + d]);
                dot = fmaf(qv[d], kk.x, dot);
                dot = fmaf(qv[d + 1], kk.y, dot);
                dot = fmaf(qv[d + 2], kk.z, dot);
                dot = fmaf(qv[d + 3], kk.w, dot);
            }
            const float logit = fmaf(dot, SCALE, lcv);
            if (logit > m) {
                const float corr = expf(m - logit);
                l *= corr;
#pragma unroll
                for (int d = 0; d < 64; d++) acc[d] *= corr;
                m = logit;
            }
            const float p = expf(logit - m);
            l += p;
#pragma unroll
            for (int d = 0; d < 64; d += 4) {
                float4 vv = *reinterpret_cast<const float4*>(&vs[j * 64 + d]);
                acc[d]     = fmaf(p, vv.x, acc[d]);
                acc[d + 1] = fmaf(p, vv.y, acc[d + 1]);
                acc[d + 2] = fmaf(p, vv.z, acc[d + 2]);
                acc[d + 3] = fmaf(p, vv.w, acc[d + 3]);
            }
        }
    }

    const float inv = 1.f / l;
    float* op = g_ao + ((size_t)bh * Ssz << 6) + ((size_t)myq << 6);
#pragma unroll
    for (int d = 0; d < 64; d += 4) {
        float4 r = make_float4(acc[d] * inv, acc[d + 1] * inv, acc[d + 2] * inv, acc[d + 3] * inv);
        *reinterpret_cast<float4*>(op + d) = r;
    }
}

// ---------------------------------------------------------------------------
extern "C" void kernel_launch(void* const* d_in, const int* in_sizes, int n_in,
                              void* d_out, int out_size)
{
    const float* query = (const float*)d_in[0];
    const float* key   = (const float*)d_in[1];
    const float* value = (const float*)d_in[2];
    const float* Wq    = (const float*)d_in[3];
    const float* bq    = (const float*)d_in[4];
    const float* Wk    = (const float*)d_in[5];
    const float* bk    = (const float*)d_in[6];
    const float* Wv    = (const float*)d_in[7];
    const float* bv    = (const float*)d_in[8];
    const float* Wo    = (const float*)d_in[9];
    const float* bo    = (const float*)d_in[10];
    const float* temp  = (const float*)d_in[11];
    float* out = (float*)d_out;

    const dim3 ggrid(Esz / GBN, Msz / GBM);         // (8, 128)
    const int inp_blocks = (Msz * Esz / 4) / 256;   // 16384
    const int w_blocks   = (Esz * Esz / 4) / 256;   // 1024

    // Q projection
    split_kernel<0><<<inp_blocks, 256>>>(query, Msz * Esz / 4);
    split_kernel<1><<<w_blocks,   256>>>(Wq,    Esz * Esz / 4);
    gemm_mma_kernel<0><<<ggrid, 256>>>(bq, nullptr);
    // K projection
    split_kernel<0><<<inp_blocks, 256>>>(key, Msz * Esz / 4);
    split_kernel<1><<<w_blocks,   256>>>(Wk,  Esz * Esz / 4);
    gemm_mma_kernel<2><<<ggrid, 256>>>(bk, nullptr);
    // V projection
    split_kernel<0><<<inp_blocks, 256>>>(value, Msz * Esz / 4);
    split_kernel<1><<<w_blocks,   256>>>(Wv,    Esz * Esz / 4);
    gemm_mma_kernel<3><<<ggrid, 256>>>(bv, nullptr);

    qmean_kernel<<<Bsz * Hsz, 512>>>();
    score_kernel<<<Bsz * Hsz * NWv, 256>>>(temp);
    topk_kernel<<<Bsz * Hsz, 32>>>();
    attn_kernel<<<dim3(Ssz / 128, Bsz * Hsz), 128>>>();

    // Output projection
    split_ao_kernel<<<(Msz * 256) / 256, 256>>>();
    split_kernel<1><<<w_blocks, 256>>>(Wo, Esz * Esz / 4);
    gemm_mma_kernel<1><<<ggrid, 256>>>(bo, out);
}